// round 11
// baseline (speedup 1.0000x reference)
#include <cuda_runtime.h>
#include <cuda_fp16.h>
#include <cstdint>

// Problem constants (match reference: N, E, F_IN, H, D)
#define NNODES 50000
#define NEDGES 800000
#define FDIM   128      // F_IN == H*D == 128
#define NHEADS 4
#define HDIM   32
#define SCAN_NB ((NNODES + 1023) / 1024)   // 49

// ---------------- device scratch (no allocations allowed) ----------------
__device__ __align__(16) __half g_hh[NNODES * FDIM];   // x @ W in fp16 (12.8 MB)
__device__ float g_alpha_l[NNODES * NHEADS];
__device__ float g_alpha_r[NNODES * NHEADS];
__device__ int   g_cnt[NNODES];                        // histogram
__device__ int   g_off[NNODES];                        // block-local excl scan; cursor
__device__ int   g_src[NEDGES];                        // src per edge, sorted by dst
__device__ int   g_bsum[SCAN_NB];
__device__ int   g_boff[SCAN_NB];
__device__ int   g_sync1;                              // scan last-block ticket
__device__ int   g_is64;                               // edge dtype flag
// W in tf32 mma-fragment layout: [ks(16)][nt(16)][lane(32)] -> (b0,b1)
__device__ __align__(16) uint2 g_wf[16 * 16 * 32];     // 64 KB

__device__ __forceinline__ int clamp_node(int v) {
    v = v < 0 ? 0 : v;
    return v >= NNODES ? NNODES - 1 : v;
}

__device__ __forceinline__ uint32_t f2tf32(float f) {
    uint32_t r;
    asm("cvt.rna.tf32.f32 %0, %1;" : "=r"(r) : "f"(f));
    return r;
}

__device__ __forceinline__ void mma_tf32(float4& d, const uint32_t a0, const uint32_t a1,
                                         const uint32_t a2, const uint32_t a3,
                                         uint32_t b0, uint32_t b1) {
    asm volatile(
        "mma.sync.aligned.m16n8k8.row.col.f32.tf32.tf32.f32 "
        "{%0,%1,%2,%3}, {%4,%5,%6,%7}, {%8,%9}, {%0,%1,%2,%3};"
        : "+f"(d.x), "+f"(d.y), "+f"(d.z), "+f"(d.w)
        : "r"(a0), "r"(a1), "r"(a2), "r"(a3), "r"(b0), "r"(b1));
}

// ---------------- K0 (fused): zero hist + W->tf32 fragments + probe + sync reset ----
__global__ void k_init(const int* __restrict__ ei32, const float* __restrict__ W) {
    int t = blockIdx.x * blockDim.x + threadIdx.x;
    if (t < NNODES) g_cnt[t] = 0;
    if (t == 0) g_sync1 = 0;
    if (t < 16 * 16 * 32) {
        int lane = t & 31;
        int tile = t >> 5;
        int nt = tile & 15;
        int ks = tile >> 4;
        int krow = ks * 8 + (lane & 3);
        int col  = nt * 8 + (lane >> 2);
        uint2 b;
        b.x = f2tf32(W[krow * FDIM + col]);
        b.y = f2tf32(W[(krow + 4) * FDIM + col]);
        g_wf[t] = b;
    }
    if (blockIdx.x == 0 && threadIdx.x < 32) {
        // int64-LE edge data (values < 50000) => all odd int32 words zero
        int v = ei32[2 * threadIdx.x + 1];
        unsigned nz = __ballot_sync(0xffffffffu, v != 0);
        if (threadIdx.x == 0) g_is64 = (nz == 0u) ? 1 : 0;
    }
}

// ---------------- K1: histogram of destinations ----------------
__global__ void k_hist(const int* __restrict__ ei32) {
    int i = blockIdx.x * blockDim.x + threadIdx.x;
    if (i < NEDGES) {
        int idx = NEDGES + i;
        int to = g_is64 ? ei32[2 * idx] : ei32[idx];
        atomicAdd(&g_cnt[clamp_node(to)], 1);
    }
}

// ---------------- K2: block-local exclusive scan + last-block scans block sums ----
__global__ __launch_bounds__(1024) void k_scan1() {
    __shared__ int wsum[32];
    __shared__ int s_last;
    __shared__ int w0t;
    const int tid = threadIdx.x;
    const int lane = tid & 31, wid = tid >> 5;
    const int i = blockIdx.x * 1024 + tid;

    int v = (i < NNODES) ? g_cnt[i] : 0;
    int x = v;
    #pragma unroll
    for (int o = 1; o < 32; o <<= 1) {
        int t = __shfl_up_sync(0xffffffffu, x, o);
        if (lane >= o) x += t;
    }
    if (lane == 31) wsum[wid] = x;
    __syncthreads();
    if (wid == 0) {
        int x2 = wsum[lane];
        #pragma unroll
        for (int o = 1; o < 32; o <<= 1) {
            int t = __shfl_up_sync(0xffffffffu, x2, o);
            if (lane >= o) x2 += t;
        }
        wsum[lane] = x2;
    }
    __syncthreads();
    int add = (wid > 0) ? wsum[wid - 1] : 0;
    int incl = x + add;
    if (i < NNODES) g_off[i] = incl - v;            // block-local exclusive
    if (tid == 1023) {
        g_bsum[blockIdx.x] = incl;
        __threadfence();
        int t = atomicAdd(&g_sync1, 1);
        s_last = (t == (int)gridDim.x - 1);
    }
    __syncthreads();

    if (s_last) {                                   // fold former k_scan2
        int v2 = 0, x2 = 0;
        if (tid < 64) {
            v2 = (tid < SCAN_NB) ? g_bsum[tid] : 0;
            x2 = v2;
            #pragma unroll
            for (int o = 1; o < 32; o <<= 1) {
                int t = __shfl_up_sync(0xffffffffu, x2, o);
                if (lane >= o) x2 += t;
            }
            if (wid == 0 && lane == 31) w0t = x2;
        }
        __syncthreads();
        if (tid < 64) {
            int base = (wid == 1) ? w0t : 0;
            if (tid < SCAN_NB) g_boff[tid] = base + x2 - v2;   // exclusive block offsets
        }
    }
}

// ---------------- K3: scatter edges; g_off doubles as cursor ----------------
// pos = boff[blk(to)] + atomicAdd(&g_off[to], 1). Afterwards
// g_off[n] + g_boff[blk(n)] == END offset of node n (== start of n+1).
__global__ void k_scatter(const int* __restrict__ ei32) {
    int i = blockIdx.x * blockDim.x + threadIdx.x;
    if (i < NEDGES) {
        int is64 = g_is64;
        int from = is64 ? ei32[2 * i]            : ei32[i];
        int to   = is64 ? ei32[2 * (NEDGES + i)] : ei32[NEDGES + i];
        from = clamp_node(from);
        to   = clamp_node(to);
        int pos = g_boff[to >> 10] + atomicAdd(&g_off[to], 1);
        pos = pos < 0 ? 0 : (pos >= NEDGES ? NEDGES - 1 : pos);
        g_src[pos] = from;
    }
}

// ---------------- K4: tensor-core GEMM h = x @ W + fused alpha ----------------
// mma.sync m16n8k8 tf32; x split hi+lo (exact), W pre-rounded to tf32 (g_wf).
// h stored as fp16; alpha from fp32 accs.
__global__ __launch_bounds__(256) void k_gemm(const float* __restrict__ x,
                                              const float* __restrict__ att_l,
                                              const float* __restrict__ att_r) {
    const int wid  = threadIdx.x >> 5;
    const int lane = threadIdx.x & 31;
    const int g = lane >> 2;          // 0..7
    const int c = lane & 3;           // 0..3
    const int row0 = blockIdx.x * 128 + wid * 16;

    const int rA0 = min(row0 + g,     NNODES - 1);
    const int rA1 = min(row0 + g + 8, NNODES - 1);
    const float* xr0 = x + rA0 * FDIM;
    const float* xr1 = x + rA1 * FDIM;

    float4 acc[16];
    #pragma unroll
    for (int nt = 0; nt < 16; nt++) acc[nt] = make_float4(0.f, 0.f, 0.f, 0.f);

    #pragma unroll 4
    for (int ks = 0; ks < 16; ks++) {
        const int k0 = ks * 8;
        float v0 = xr0[k0 + c];
        float v1 = xr1[k0 + c];
        float v2 = xr0[k0 + c + 4];
        float v3 = xr1[k0 + c + 4];
        uint32_t h0 = f2tf32(v0), h1 = f2tf32(v1), h2 = f2tf32(v2), h3 = f2tf32(v3);
        uint32_t l0 = f2tf32(v0 - __uint_as_float(h0));
        uint32_t l1 = f2tf32(v1 - __uint_as_float(h1));
        uint32_t l2 = f2tf32(v2 - __uint_as_float(h2));
        uint32_t l3 = f2tf32(v3 - __uint_as_float(h3));

        const uint2* bf = g_wf + (ks * 16) * 32 + lane;
        #pragma unroll
        for (int nt = 0; nt < 16; nt++) {
            uint2 b = bf[nt * 32];
            mma_tf32(acc[nt], h0, h1, h2, h3, b.x, b.y);
            mma_tf32(acc[nt], l0, l1, l2, l3, b.x, b.y);
        }
    }

    const bool ok0 = (row0 + g)     < NNODES;
    const bool ok1 = (row0 + g + 8) < NNODES;
    __half* hr0 = g_hh + (row0 + g) * FDIM;
    __half* hr1 = g_hh + (row0 + g + 8) * FDIM;
    #pragma unroll
    for (int nt = 0; nt < 16; nt++) {
        int col = nt * 8 + 2 * c;
        if (ok0) *(__half2*)(hr0 + col) = __floats2half2_rn(acc[nt].x, acc[nt].y);
        if (ok1) *(__half2*)(hr1 + col) = __floats2half2_rn(acc[nt].z, acc[nt].w);
    }

    #pragma unroll
    for (int hd = 0; hd < NHEADS; hd++) {
        float plg = 0.f, plg8 = 0.f, prg = 0.f, prg8 = 0.f;
        #pragma unroll
        for (int j = 0; j < 4; j++) {
            int nt = hd * 4 + j;
            int col = nt * 8 + 2 * c;
            float2 al2 = *(const float2*)(att_l + col);
            float2 ar2 = *(const float2*)(att_r + col);
            plg  += acc[nt].x * al2.x + acc[nt].y * al2.y;
            plg8 += acc[nt].z * al2.x + acc[nt].w * al2.y;
            prg  += acc[nt].x * ar2.x + acc[nt].y * ar2.y;
            prg8 += acc[nt].z * ar2.x + acc[nt].w * ar2.y;
        }
        #pragma unroll
        for (int o = 1; o <= 2; o <<= 1) {
            plg  += __shfl_xor_sync(0xffffffffu, plg,  o);
            plg8 += __shfl_xor_sync(0xffffffffu, plg8, o);
            prg  += __shfl_xor_sync(0xffffffffu, prg,  o);
            prg8 += __shfl_xor_sync(0xffffffffu, prg8, o);
        }
        if (c == 0) {
            if (ok0) {
                g_alpha_l[(row0 + g) * NHEADS + hd] = plg;
                g_alpha_r[(row0 + g) * NHEADS + hd] = prg;
            }
            if (ok1) {
                g_alpha_l[(row0 + g + 8) * NHEADS + hd] = plg8;
                g_alpha_r[(row0 + g + 8) * NHEADS + hd] = prg8;
            }
        }
    }
}

// ---------------- K5: per-destination softmax-weighted aggregation ----------------
// one warp per destination; unroll x4 (batched independent loads for MLP).
// Ranges: end[n] = g_off[n] + g_boff[n>>10]; start[n] = end[n-1] (0 for n=0).
__global__ __launch_bounds__(256) void k_agg(const float* __restrict__ bias,
                                             float* __restrict__ out) {
    int n = blockIdx.x * 8 + (threadIdx.x >> 5);
    int lane = threadIdx.x & 31;
    if (n >= NNODES) return;

    const int head = lane >> 3;
    const float ar = g_alpha_r[n * NHEADS + head];
    const int off1 = g_off[n] + g_boff[n >> 10];
    const int off0 = (n == 0) ? 0 : (g_off[n - 1] + g_boff[(n - 1) >> 10]);

    float4 acc = make_float4(0.f, 0.f, 0.f, 0.f);
    float den = 0.f;
    const uint2* h2 = (const uint2*)g_hh;   // lane reads 4 halves (8B)

    int e = off0;
    for (; e + 3 < off1; e += 4) {
        int s0 = g_src[e];
        int s1 = g_src[e + 1];
        int s2 = g_src[e + 2];
        int s3 = g_src[e + 3];
        float a0 = g_alpha_l[s0 * NHEADS + head];
        float a1 = g_alpha_l[s1 * NHEADS + head];
        float a2 = g_alpha_l[s2 * NHEADS + head];
        float a3 = g_alpha_l[s3 * NHEADS + head];
        uint2 u0 = h2[s0 * 32 + lane];
        uint2 u1 = h2[s1 * 32 + lane];
        uint2 u2 = h2[s2 * 32 + lane];
        uint2 u3 = h2[s3 * 32 + lane];
        a0 += ar; a1 += ar; a2 += ar; a3 += ar;
        a0 = (a0 > 0.f) ? a0 : 0.2f * a0;
        a1 = (a1 > 0.f) ? a1 : 0.2f * a1;
        a2 = (a2 > 0.f) ? a2 : 0.2f * a2;
        a3 = (a3 > 0.f) ? a3 : 0.2f * a3;
        float w0 = __expf(a0);
        float w1 = __expf(a1);
        float w2 = __expf(a2);
        float w3 = __expf(a3);
        float2 p;
        p = __half22float2(*(const __half2*)&u0.x);
        acc.x = fmaf(w0, p.x, acc.x); acc.y = fmaf(w0, p.y, acc.y);
        p = __half22float2(*(const __half2*)&u0.y);
        acc.z = fmaf(w0, p.x, acc.z); acc.w = fmaf(w0, p.y, acc.w);
        p = __half22float2(*(const __half2*)&u1.x);
        acc.x = fmaf(w1, p.x, acc.x); acc.y = fmaf(w1, p.y, acc.y);
        p = __half22float2(*(const __half2*)&u1.y);
        acc.z = fmaf(w1, p.x, acc.z); acc.w = fmaf(w1, p.y, acc.w);
        p = __half22float2(*(const __half2*)&u2.x);
        acc.x = fmaf(w2, p.x, acc.x); acc.y = fmaf(w2, p.y, acc.y);
        p = __half22float2(*(const __half2*)&u2.y);
        acc.z = fmaf(w2, p.x, acc.z); acc.w = fmaf(w2, p.y, acc.w);
        p = __half22float2(*(const __half2*)&u3.x);
        acc.x = fmaf(w3, p.x, acc.x); acc.y = fmaf(w3, p.y, acc.y);
        p = __half22float2(*(const __half2*)&u3.y);
        acc.z = fmaf(w3, p.x, acc.z); acc.w = fmaf(w3, p.y, acc.w);
        den += (w0 + w1) + (w2 + w3);
    }
    for (; e < off1; e++) {
        int s = g_src[e];
        float a = g_alpha_l[s * NHEADS + head] + ar;
        a = (a > 0.f) ? a : 0.2f * a;
        float w = __expf(a);
        uint2 u = h2[s * 32 + lane];
        float2 p0 = __half22float2(*(const __half2*)&u.x);
        float2 p1 = __half22float2(*(const __half2*)&u.y);
        acc.x = fmaf(w, p0.x, acc.x);
        acc.y = fmaf(w, p0.y, acc.y);
        acc.z = fmaf(w, p1.x, acc.z);
        acc.w = fmaf(w, p1.y, acc.w);
        den += w;
    }

    float inv = 1.f / (den + 1e-9f);
    float b0 = bias[lane * 4 + 0], b1 = bias[lane * 4 + 1];
    float b2 = bias[lane * 4 + 2], b3 = bias[lane * 4 + 3];
    float4 o;
    o.x = fmaf(acc.x, inv, b0);
    o.y = fmaf(acc.y, inv, b1);
    o.z = fmaf(acc.z, inv, b2);
    o.w = fmaf(acc.w, inv, b3);
    ((float4*)out)[n * 32 + lane] = o;
}

// ---------------- launcher ----------------
extern "C" void kernel_launch(void* const* d_in, const int* in_sizes, int n_in,
                              void* d_out, int out_size) {
    int ix = -1, ie = -1, iw = -1;
    int small_idx[3] = {-1, -1, -1};
    int ns = 0;
    for (int i = 0; i < n_in; i++) {
        int sz = in_sizes[i];
        if      (sz == NNODES * FDIM) ix = i;
        else if (sz == 2 * NEDGES)    ie = i;
        else if (sz == FDIM * FDIM)   iw = i;
        else if (sz == FDIM && ns < 3) small_idx[ns++] = i;
    }
    if (ix < 0 || ie < 0 || iw < 0 || ns < 3) {
        ix = 0; ie = 1; iw = 2;
        small_idx[0] = 3; small_idx[1] = 4; small_idx[2] = 5;
    }

    const float* x     = (const float*)d_in[ix];
    const int*   ei32  = (const int*)d_in[ie];
    const float* W     = (const float*)d_in[iw];
    const float* att_l = (const float*)d_in[small_idx[0]];
    const float* att_r = (const float*)d_in[small_idx[1]];
    const float* bias  = (const float*)d_in[small_idx[2]];
    float*       out   = (float*)d_out;

    k_init<<<(NNODES + 255) / 256, 256>>>(ei32, W);
    k_hist<<<(NEDGES + 255) / 256, 256>>>(ei32);
    k_scan1<<<SCAN_NB, 1024>>>();
    k_scatter<<<(NEDGES + 255) / 256, 256>>>(ei32);
    k_gemm<<<(NNODES + 127) / 128, 256>>>(x, att_l, att_r);
    k_agg<<<(NNODES + 7) / 8, 256>>>(bias, out);
}

// round 12
// speedup vs baseline: 1.3099x; 1.3099x over previous
#include <cuda_runtime.h>
#include <cuda_fp16.h>
#include <cstdint>

// Problem constants (match reference: N, E, F_IN, H, D)
#define NNODES 50000
#define NEDGES 800000
#define FDIM   128      // F_IN == H*D == 128
#define NHEADS 4
#define HDIM   32
#define SCAN_NB ((NNODES + 1023) / 1024)   // 49

// ---------------- device scratch (no allocations allowed) ----------------
__device__ __align__(16) __half g_hh[NNODES * FDIM];   // x @ W in fp16 (12.8 MB)
__device__ float g_alpha_l[NNODES * NHEADS];
__device__ float g_alpha_r[NNODES * NHEADS];
__device__ int   g_cnt[NNODES];                        // histogram
__device__ int   g_off[NNODES];                        // block-local excl scan; cursor
__device__ int   g_src[NEDGES];                        // src per edge, sorted by dst
__device__ int   g_bsum[SCAN_NB];
__device__ int   g_boff[SCAN_NB];
__device__ int   g_sync1;                              // scan last-block ticket
__device__ int   g_is64;                               // edge dtype flag
// W in tf32 mma-fragment layout: [ks(16)][nt(16)][lane(32)] -> (b0,b1)
__device__ __align__(16) uint2 g_wf[16 * 16 * 32];     // 64 KB

__device__ __forceinline__ int clamp_node(int v) {
    v = v < 0 ? 0 : v;
    return v >= NNODES ? NNODES - 1 : v;
}

__device__ __forceinline__ uint32_t f2tf32(float f) {
    uint32_t r;
    asm("cvt.rna.tf32.f32 %0, %1;" : "=r"(r) : "f"(f));
    return r;
}

__device__ __forceinline__ void mma_tf32(float4& d, const uint32_t a0, const uint32_t a1,
                                         const uint32_t a2, const uint32_t a3,
                                         uint32_t b0, uint32_t b1) {
    asm volatile(
        "mma.sync.aligned.m16n8k8.row.col.f32.tf32.tf32.f32 "
        "{%0,%1,%2,%3}, {%4,%5,%6,%7}, {%8,%9}, {%0,%1,%2,%3};"
        : "+f"(d.x), "+f"(d.y), "+f"(d.z), "+f"(d.w)
        : "r"(a0), "r"(a1), "r"(a2), "r"(a3), "r"(b0), "r"(b1));
}

// ---------------- K0 (fused): zero hist + W->tf32 fragments + probe + sync reset ----
__global__ void k_init(const int* __restrict__ ei32, const float* __restrict__ W) {
    int t = blockIdx.x * blockDim.x + threadIdx.x;
    if (t < NNODES) g_cnt[t] = 0;
    if (t == 0) g_sync1 = 0;
    if (t < 16 * 16 * 32) {
        int lane = t & 31;
        int tile = t >> 5;
        int nt = tile & 15;
        int ks = tile >> 4;
        int krow = ks * 8 + (lane & 3);
        int col  = nt * 8 + (lane >> 2);
        uint2 b;
        b.x = f2tf32(W[krow * FDIM + col]);
        b.y = f2tf32(W[(krow + 4) * FDIM + col]);
        g_wf[t] = b;
    }
    if (blockIdx.x == 0 && threadIdx.x < 32) {
        // int64-LE edge data (values < 50000) => all odd int32 words zero
        int v = ei32[2 * threadIdx.x + 1];
        unsigned nz = __ballot_sync(0xffffffffu, v != 0);
        if (threadIdx.x == 0) g_is64 = (nz == 0u) ? 1 : 0;
    }
}

// ---------------- K1: histogram of destinations ----------------
__global__ void k_hist(const int* __restrict__ ei32) {
    int i = blockIdx.x * blockDim.x + threadIdx.x;
    if (i < NEDGES) {
        int idx = NEDGES + i;
        int to = g_is64 ? ei32[2 * idx] : ei32[idx];
        atomicAdd(&g_cnt[clamp_node(to)], 1);
    }
}

// ---------------- K2: block-local exclusive scan + last-block scans block sums ----
__global__ __launch_bounds__(1024) void k_scan1() {
    __shared__ int wsum[32];
    __shared__ int s_last;
    __shared__ int w0t;
    const int tid = threadIdx.x;
    const int lane = tid & 31, wid = tid >> 5;
    const int i = blockIdx.x * 1024 + tid;

    int v = (i < NNODES) ? g_cnt[i] : 0;
    int x = v;
    #pragma unroll
    for (int o = 1; o < 32; o <<= 1) {
        int t = __shfl_up_sync(0xffffffffu, x, o);
        if (lane >= o) x += t;
    }
    if (lane == 31) wsum[wid] = x;
    __syncthreads();
    if (wid == 0) {
        int x2 = wsum[lane];
        #pragma unroll
        for (int o = 1; o < 32; o <<= 1) {
            int t = __shfl_up_sync(0xffffffffu, x2, o);
            if (lane >= o) x2 += t;
        }
        wsum[lane] = x2;
    }
    __syncthreads();
    int add = (wid > 0) ? wsum[wid - 1] : 0;
    int incl = x + add;
    if (i < NNODES) g_off[i] = incl - v;            // block-local exclusive
    if (tid == 1023) {
        g_bsum[blockIdx.x] = incl;
        __threadfence();
        int t = atomicAdd(&g_sync1, 1);
        s_last = (t == (int)gridDim.x - 1);
    }
    __syncthreads();

    if (s_last) {                                   // fold former k_scan2
        int v2 = 0, x2 = 0;
        if (tid < 64) {
            v2 = (tid < SCAN_NB) ? g_bsum[tid] : 0;
            x2 = v2;
            #pragma unroll
            for (int o = 1; o < 32; o <<= 1) {
                int t = __shfl_up_sync(0xffffffffu, x2, o);
                if (lane >= o) x2 += t;
            }
            if (wid == 0 && lane == 31) w0t = x2;
        }
        __syncthreads();
        if (tid < 64) {
            int base = (wid == 1) ? w0t : 0;
            if (tid < SCAN_NB) g_boff[tid] = base + x2 - v2;   // exclusive block offsets
        }
    }
}

// ---------------- K3: scatter edges; g_off doubles as cursor ----------------
// pos = boff[blk(to)] + atomicAdd(&g_off[to], 1). Afterwards
// g_off[n] + g_boff[blk(n)] == END offset of node n (== start of n+1).
__global__ void k_scatter(const int* __restrict__ ei32) {
    int i = blockIdx.x * blockDim.x + threadIdx.x;
    if (i < NEDGES) {
        int is64 = g_is64;
        int from = is64 ? ei32[2 * i]            : ei32[i];
        int to   = is64 ? ei32[2 * (NEDGES + i)] : ei32[NEDGES + i];
        from = clamp_node(from);
        to   = clamp_node(to);
        int pos = g_boff[to >> 10] + atomicAdd(&g_off[to], 1);
        pos = pos < 0 ? 0 : (pos >= NEDGES ? NEDGES - 1 : pos);
        g_src[pos] = from;
    }
}

// ---------------- K4: tensor-core GEMM h = x @ W + fused alpha ----------------
// mma.sync m16n8k8 tf32; x split hi+lo (exact), W pre-rounded to tf32 (g_wf).
// h stored as fp16; alpha from fp32 accs.
__global__ __launch_bounds__(256) void k_gemm(const float* __restrict__ x,
                                              const float* __restrict__ att_l,
                                              const float* __restrict__ att_r) {
    const int wid  = threadIdx.x >> 5;
    const int lane = threadIdx.x & 31;
    const int g = lane >> 2;          // 0..7
    const int c = lane & 3;           // 0..3
    const int row0 = blockIdx.x * 128 + wid * 16;

    const int rA0 = min(row0 + g,     NNODES - 1);
    const int rA1 = min(row0 + g + 8, NNODES - 1);
    const float* xr0 = x + rA0 * FDIM;
    const float* xr1 = x + rA1 * FDIM;

    float4 acc[16];
    #pragma unroll
    for (int nt = 0; nt < 16; nt++) acc[nt] = make_float4(0.f, 0.f, 0.f, 0.f);

    #pragma unroll 4
    for (int ks = 0; ks < 16; ks++) {
        const int k0 = ks * 8;
        float v0 = xr0[k0 + c];
        float v1 = xr1[k0 + c];
        float v2 = xr0[k0 + c + 4];
        float v3 = xr1[k0 + c + 4];
        uint32_t h0 = f2tf32(v0), h1 = f2tf32(v1), h2 = f2tf32(v2), h3 = f2tf32(v3);
        uint32_t l0 = f2tf32(v0 - __uint_as_float(h0));
        uint32_t l1 = f2tf32(v1 - __uint_as_float(h1));
        uint32_t l2 = f2tf32(v2 - __uint_as_float(h2));
        uint32_t l3 = f2tf32(v3 - __uint_as_float(h3));

        const uint2* bf = g_wf + (ks * 16) * 32 + lane;
        #pragma unroll
        for (int nt = 0; nt < 16; nt++) {
            uint2 b = bf[nt * 32];
            mma_tf32(acc[nt], h0, h1, h2, h3, b.x, b.y);
            mma_tf32(acc[nt], l0, l1, l2, l3, b.x, b.y);
        }
    }

    const bool ok0 = (row0 + g)     < NNODES;
    const bool ok1 = (row0 + g + 8) < NNODES;
    __half* hr0 = g_hh + (row0 + g) * FDIM;
    __half* hr1 = g_hh + (row0 + g + 8) * FDIM;
    #pragma unroll
    for (int nt = 0; nt < 16; nt++) {
        int col = nt * 8 + 2 * c;
        if (ok0) *(__half2*)(hr0 + col) = __floats2half2_rn(acc[nt].x, acc[nt].y);
        if (ok1) *(__half2*)(hr1 + col) = __floats2half2_rn(acc[nt].z, acc[nt].w);
    }

    #pragma unroll
    for (int hd = 0; hd < NHEADS; hd++) {
        float plg = 0.f, plg8 = 0.f, prg = 0.f, prg8 = 0.f;
        #pragma unroll
        for (int j = 0; j < 4; j++) {
            int nt = hd * 4 + j;
            int col = nt * 8 + 2 * c;
            float2 al2 = *(const float2*)(att_l + col);
            float2 ar2 = *(const float2*)(att_r + col);
            plg  += acc[nt].x * al2.x + acc[nt].y * al2.y;
            plg8 += acc[nt].z * al2.x + acc[nt].w * al2.y;
            prg  += acc[nt].x * ar2.x + acc[nt].y * ar2.y;
            prg8 += acc[nt].z * ar2.x + acc[nt].w * ar2.y;
        }
        #pragma unroll
        for (int o = 1; o <= 2; o <<= 1) {
            plg  += __shfl_xor_sync(0xffffffffu, plg,  o);
            plg8 += __shfl_xor_sync(0xffffffffu, plg8, o);
            prg  += __shfl_xor_sync(0xffffffffu, prg,  o);
            prg8 += __shfl_xor_sync(0xffffffffu, prg8, o);
        }
        if (c == 0) {
            if (ok0) {
                g_alpha_l[(row0 + g) * NHEADS + hd] = plg;
                g_alpha_r[(row0 + g) * NHEADS + hd] = prg;
            }
            if (ok1) {
                g_alpha_l[(row0 + g + 8) * NHEADS + hd] = plg8;
                g_alpha_r[(row0 + g + 8) * NHEADS + hd] = prg8;
            }
        }
    }
}

// ---------------- K5: per-destination softmax-weighted aggregation ----------------
// one warp per destination; unroll x2 (exact R9 body).
// Ranges: end[n] = g_off[n] + g_boff[n>>10]; start[n] = end[n-1] (0 for n=0).
__global__ __launch_bounds__(256) void k_agg(const float* __restrict__ bias,
                                             float* __restrict__ out) {
    int n = blockIdx.x * 8 + (threadIdx.x >> 5);
    int lane = threadIdx.x & 31;
    if (n >= NNODES) return;

    const int head = lane >> 3;
    const float ar = g_alpha_r[n * NHEADS + head];
    const int off1 = g_off[n] + g_boff[n >> 10];
    const int off0 = (n == 0) ? 0 : (g_off[n - 1] + g_boff[(n - 1) >> 10]);

    float4 acc = make_float4(0.f, 0.f, 0.f, 0.f);
    float den = 0.f;
    const uint2* h2 = (const uint2*)g_hh;   // lane reads 4 halves (8B)

    int e = off0;
    for (; e + 1 < off1; e += 2) {
        int s0 = g_src[e];
        int s1 = g_src[e + 1];
        float a0 = g_alpha_l[s0 * NHEADS + head] + ar;
        float a1 = g_alpha_l[s1 * NHEADS + head] + ar;
        uint2 u0 = h2[s0 * 32 + lane];
        uint2 u1 = h2[s1 * 32 + lane];
        a0 = (a0 > 0.f) ? a0 : 0.2f * a0;
        a1 = (a1 > 0.f) ? a1 : 0.2f * a1;
        float w0 = __expf(a0);
        float w1 = __expf(a1);
        float2 p00 = __half22float2(*(const __half2*)&u0.x);
        float2 p01 = __half22float2(*(const __half2*)&u0.y);
        float2 p10 = __half22float2(*(const __half2*)&u1.x);
        float2 p11 = __half22float2(*(const __half2*)&u1.y);
        acc.x = fmaf(w0, p00.x, fmaf(w1, p10.x, acc.x));
        acc.y = fmaf(w0, p00.y, fmaf(w1, p10.y, acc.y));
        acc.z = fmaf(w0, p01.x, fmaf(w1, p11.x, acc.z));
        acc.w = fmaf(w0, p01.y, fmaf(w1, p11.y, acc.w));
        den += w0 + w1;
    }
    if (e < off1) {
        int s = g_src[e];
        float a = g_alpha_l[s * NHEADS + head] + ar;
        a = (a > 0.f) ? a : 0.2f * a;
        float w = __expf(a);
        uint2 u = h2[s * 32 + lane];
        float2 p0 = __half22float2(*(const __half2*)&u.x);
        float2 p1 = __half22float2(*(const __half2*)&u.y);
        acc.x = fmaf(w, p0.x, acc.x);
        acc.y = fmaf(w, p0.y, acc.y);
        acc.z = fmaf(w, p1.x, acc.z);
        acc.w = fmaf(w, p1.y, acc.w);
        den += w;
    }

    float inv = 1.f / (den + 1e-9f);
    float b0 = bias[lane * 4 + 0], b1 = bias[lane * 4 + 1];
    float b2 = bias[lane * 4 + 2], b3 = bias[lane * 4 + 3];
    float4 o;
    o.x = fmaf(acc.x, inv, b0);
    o.y = fmaf(acc.y, inv, b1);
    o.z = fmaf(acc.z, inv, b2);
    o.w = fmaf(acc.w, inv, b3);
    ((float4*)out)[n * 32 + lane] = o;
}

// ---------------- launcher ----------------
extern "C" void kernel_launch(void* const* d_in, const int* in_sizes, int n_in,
                              void* d_out, int out_size) {
    int ix = -1, ie = -1, iw = -1;
    int small_idx[3] = {-1, -1, -1};
    int ns = 0;
    for (int i = 0; i < n_in; i++) {
        int sz = in_sizes[i];
        if      (sz == NNODES * FDIM) ix = i;
        else if (sz == 2 * NEDGES)    ie = i;
        else if (sz == FDIM * FDIM)   iw = i;
        else if (sz == FDIM && ns < 3) small_idx[ns++] = i;
    }
    if (ix < 0 || ie < 0 || iw < 0 || ns < 3) {
        ix = 0; ie = 1; iw = 2;
        small_idx[0] = 3; small_idx[1] = 4; small_idx[2] = 5;
    }

    const float* x     = (const float*)d_in[ix];
    const int*   ei32  = (const int*)d_in[ie];
    const float* W     = (const float*)d_in[iw];
    const float* att_l = (const float*)d_in[small_idx[0]];
    const float* att_r = (const float*)d_in[small_idx[1]];
    const float* bias  = (const float*)d_in[small_idx[2]];
    float*       out   = (float*)d_out;

    k_init<<<(NNODES + 255) / 256, 256>>>(ei32, W);
    k_hist<<<(NEDGES + 255) / 256, 256>>>(ei32);
    k_scan1<<<SCAN_NB, 1024>>>();
    k_scatter<<<(NEDGES + 255) / 256, 256>>>(ei32);
    k_gemm<<<(NNODES + 127) / 128, 256>>>(x, att_l, att_r);
    k_agg<<<(NNODES + 7) / 8, 256>>>(bias, out);
}